// round 8
// baseline (speedup 1.0000x reference)
#include <cuda_runtime.h>
#include <cstdint>

// Problem constants (shapes fixed by the dataset problem)
#define ROWS 64            // B*N
#define PP   147456        // H*W
#define KCLS 3
#define NBIN 4096
#define THREADS 256

// k1 chunking
#define CHUNKS1 16
#define CHUNK1  (PP / CHUNKS1)           // 9216
#define ITERS1  (CHUNK1 / (THREADS*4))   // 9

// k3 chunking (finer: fewer regs, better occupancy/wave balance)
#define CHUNKS3 48
#define CHUNK3  (PP / CHUNKS3)           // 3072
#define ITERS3  (CHUNK3 / (THREADS*4))   // 3

#define FX_SCALE  4194304.0f             // 2^22 per-element fixed point
#define TOT_MUL   256ull                 // 2^22 -> 2^30 for g_total
#define FXD       1073741824.0           // 2^30

// -------- scratch (no allocations allowed; device globals; self-cleaning) ----
__device__ float g_nll [(size_t)ROWS * PP];
__device__ float g_side[(size_t)ROWS * PP];          // segmented by k3 chunking
__device__ unsigned int g_hist[ROWS * NBIN];         // zeroed by k2 after use
__device__ unsigned int g_segcnt[ROWS * CHUNKS3];    // overwritten by k3 each run
__device__ int g_bstar[ROWS];                        // overwritten by k2
__device__ int g_needed[ROWS];                       // overwritten by k2
__device__ unsigned long long g_total;               // zeroed by k5 after use

__device__ __forceinline__ unsigned int nbits(float v) {
    return (v > 0.0f) ? __float_as_uint(v) : 0u;     // nll >= 0
}

__device__ __forceinline__ unsigned long long fx_of(float v) {
    float c = fminf(v, 64.0f);                       // 46-bit safety cap
    return (unsigned long long)(c * FX_SCALE + 0.5f);
}

__device__ __forceinline__ float nllsel(int t, float a, float b, float c) {
    if (t == 255) return 0.0f;                       // ignore_index
    float v = (t == 0) ? a : (t == 1) ? b : c;
    return -v;
}

__device__ __forceinline__ int decode_m(const void* sp_ptr, int has_sp) {
    double sp = 1.0;
    if (has_sp) {
        unsigned int bits = *(const unsigned int*)sp_ptr;
        if (bits < 1024u) sp = (double)(int)bits;            // int32 scalar
        else              sp = (double)__uint_as_float(bits);// float32 scalar
    }
    if (sp > 1.0) sp = 1.0;
    if (sp < 0.0) sp = 0.0;
    double md = sp * 0.15 * (double)PP + (1.0 - sp) * (double)PP;
    int m = (int)md;
    if (m < 1) m = 1;
    if (m > PP) m = PP;
    return m;
}

// -------- K1: nll compute + buffer + per-row u32 histogram --------
__global__ void __launch_bounds__(THREADS) k1_nll(const float* __restrict__ inp,
                                                  const int*   __restrict__ tgt) {
    __shared__ unsigned int sh[NBIN];                // 16 KB
    for (int i = threadIdx.x; i < NBIN; i += THREADS) sh[i] = 0u;
    __syncthreads();

    int row = blockIdx.x / CHUNKS1;
    int seg = blockIdx.x % CHUNKS1;
    size_t tbase = (size_t)row * PP + (size_t)seg * CHUNK1;
    const float* p0 = inp + (size_t)row * KCLS * PP + (size_t)seg * CHUNK1;
    const float* p1 = p0 + PP;
    const float* p2 = p0 + 2 * PP;
    const int*   tg = tgt + tbase;
    float*       ob = g_nll + tbase;

    int off0 = threadIdx.x * 4;
    int4   t4 = *(const int4*)(tg + off0);
    float4 a  = *(const float4*)(p0 + off0);
    float4 b  = *(const float4*)(p1 + off0);
    float4 c  = *(const float4*)(p2 + off0);

#pragma unroll
    for (int it = 0; it < ITERS1; ++it) {
        int4 t4n; float4 an, bn, cn;
        if (it + 1 < ITERS1) {
            int offn = (it + 1) * (THREADS * 4) + threadIdx.x * 4;
            t4n = *(const int4*)(tg + offn);
            an  = *(const float4*)(p0 + offn);
            bn  = *(const float4*)(p1 + offn);
            cn  = *(const float4*)(p2 + offn);
        }
        int off = it * (THREADS * 4) + threadIdx.x * 4;
        float4 o;
        o.x = nllsel(t4.x, a.x, b.x, c.x);
        o.y = nllsel(t4.y, a.y, b.y, c.y);
        o.z = nllsel(t4.z, a.z, b.z, c.z);
        o.w = nllsel(t4.w, a.w, b.w, c.w);
        atomicAdd(&sh[nbits(o.x) >> 19], 1u);
        atomicAdd(&sh[nbits(o.y) >> 19], 1u);
        atomicAdd(&sh[nbits(o.z) >> 19], 1u);
        atomicAdd(&sh[nbits(o.w) >> 19], 1u);
        *(float4*)(ob + off) = o;
        t4 = t4n; a = an; b = bn; c = cn;
    }
    __syncthreads();
    for (int i = threadIdx.x; i < NBIN; i += THREADS) {
        unsigned int v = sh[i];
        if (v) atomicAdd(&g_hist[row * NBIN + i], v);
    }
}

// -------- K2: threshold bin via suffix scan; zeroes g_hist after use --------
__global__ void __launch_bounds__(THREADS) k2_thresh(const void* sp_ptr, int has_sp) {
    int row = blockIdx.x;
    __shared__ unsigned int sh[NBIN];
    __shared__ unsigned int cs[THREADS];
    for (int i = threadIdx.x; i < NBIN; i += THREADS) {
        sh[i] = g_hist[row * NBIN + i];
        g_hist[row * NBIN + i] = 0u;                 // self-clean for next replay
    }
    __syncthreads();
    unsigned s = 0;
    int base = threadIdx.x * (NBIN / THREADS);       // 16 bins each
    for (int j = 0; j < NBIN / THREADS; ++j) s += sh[base + j];
    cs[threadIdx.x] = s;
    __syncthreads();
    if (threadIdx.x == 0) {
        unsigned m = (unsigned)decode_m(sp_ptr, has_sp);
        unsigned acc = 0, above = 0;
        int bstar = 0;
        for (int j = THREADS - 1; j >= 0; --j) {
            if (acc + cs[j] >= m) {
                for (int b = j * 16 + 15; b >= j * 16; --b) {
                    acc += sh[b];
                    if (acc >= m) { bstar = b; above = acc - sh[b]; break; }
                }
                break;
            }
            acc += cs[j];
        }
        g_bstar[row]  = bstar;
        g_needed[row] = (int)m - (int)above;
    }
}

// -------- K3: fx-sum above bins; block-private compaction of threshold bin ----
__global__ void __launch_bounds__(THREADS) k3_sum() {
    int row = blockIdx.x / CHUNKS3;
    unsigned bstar = (unsigned)g_bstar[row];
    size_t tbase = (size_t)row * PP + (size_t)(blockIdx.x % CHUNKS3) * CHUNK3;
    const float4* ib = (const float4*)(g_nll + tbase);
    float* sb = g_side + tbase;                      // private segment, cap CHUNK3

    __shared__ unsigned int scnt;
    __shared__ unsigned long long wred[THREADS / 32];
    if (threadIdx.x == 0) scnt = 0u;
    __syncthreads();

    // Front-batch loads: 3 independent LDG.128 per thread.
    float4 r[ITERS3];
#pragma unroll
    for (int it = 0; it < ITERS3; ++it)
        r[it] = ib[it * THREADS + threadIdx.x];

    unsigned long long fx = 0ull;
#pragma unroll
    for (int it = 0; it < ITERS3; ++it) {
        float vv[4] = {r[it].x, r[it].y, r[it].z, r[it].w};
#pragma unroll
        for (int e = 0; e < 4; ++e) {
            float v = vv[e];
            unsigned bin = nbits(v) >> 19;
            if (bin > bstar) {
                fx += fx_of(v);
            } else if (bin == bstar) {               // rare (~2%); block-local atomic
                unsigned idx = atomicAdd(&scnt, 1u);
                sb[idx] = v;
            }
        }
    }

    // warp shuffle reduction, then one cross-warp step
#pragma unroll
    for (int o = 16; o > 0; o >>= 1)
        fx += __shfl_xor_sync(0xffffffffu, fx, o);
    int wid = threadIdx.x >> 5;
    if ((threadIdx.x & 31) == 0) wred[wid] = fx;
    __syncthreads();
    if (threadIdx.x == 0) {
        unsigned long long t = 0ull;
#pragma unroll
        for (int w = 0; w < THREADS / 32; ++w) t += wred[w];
        if (t) atomicAdd(&g_total, t * TOT_MUL);
        g_segcnt[blockIdx.x] = scnt;
    }
}

// -------- K4: exact select inside the threshold bin (2 radix levels) --------
__global__ void __launch_bounds__(THREADS) k4_side() {
    int row = blockIdx.x;
    int needed = g_needed[row];
    if (needed <= 0) return;
    int tid = threadIdx.x;

    __shared__ unsigned int segc[CHUNKS3];
    for (int i = tid; i < CHUNKS3; i += THREADS)
        segc[i] = g_segcnt[row * CHUNKS3 + i];
    __syncthreads();

    __shared__ unsigned int h[NBIN];
    __shared__ unsigned int cs[THREADS];
    __shared__ unsigned long long red[THREADS];
    __shared__ unsigned int hb[128];
    __shared__ int s_b2, s_need2, s_b3, s_need3;

    for (int i = tid; i < NBIN; i += THREADS) h[i] = 0u;
    __syncthreads();
    for (int sg = 0; sg < CHUNKS3; ++sg) {
        const float* sb = g_side + (size_t)(row * CHUNKS3 + sg) * CHUNK3;
        int cnt = (int)segc[sg];
        for (int i = tid; i < cnt; i += THREADS) {
            unsigned bits = nbits(sb[i]);
            atomicAdd(&h[(bits >> 7) & 0xFFFu], 1u);
        }
    }
    __syncthreads();
    unsigned s = 0;
    int base = tid * (NBIN / THREADS);
    for (int j = 0; j < NBIN / THREADS; ++j) s += h[base + j];
    cs[tid] = s;
    __syncthreads();
    if (tid == 0) {
        unsigned acc = 0, above = 0; int b2 = 0;
        for (int j = THREADS - 1; j >= 0; --j) {
            if (acc + cs[j] >= (unsigned)needed) {
                for (int b = j * 16 + 15; b >= j * 16; --b) {
                    acc += h[b];
                    if (acc >= (unsigned)needed) { b2 = b; above = acc - h[b]; break; }
                }
                break;
            }
            acc += cs[j];
        }
        s_b2 = b2; s_need2 = needed - (int)above;
    }
    for (int i = tid; i < 128; i += THREADS) hb[i] = 0u;
    __syncthreads();
    int b2 = s_b2, need2 = s_need2;

    unsigned long long sum1 = 0ull;
    for (int sg = 0; sg < CHUNKS3; ++sg) {
        const float* sb = g_side + (size_t)(row * CHUNKS3 + sg) * CHUNK3;
        int cnt = (int)segc[sg];
        for (int i = tid; i < cnt; i += THREADS) {
            float v = sb[i];
            unsigned bits = nbits(v);
            int b = (int)((bits >> 7) & 0xFFFu);
            if (b > b2) sum1 += fx_of(v);
            else if (b == b2) atomicAdd(&hb[bits & 0x7Fu], 1u);
        }
    }
    red[tid] = sum1;
    __syncthreads();
    for (int st = THREADS / 2; st > 0; st >>= 1) {
        if (tid < st) red[tid] += red[tid + st];
        __syncthreads();
    }
    unsigned long long sum_gt2 = red[0];   // read by all before next barrier pass
    if (tid == 0) {
        unsigned acc = 0, above = 0; int b3 = 0;
        for (int b = 127; b >= 0; --b) {
            acc += hb[b];
            if (acc >= (unsigned)need2) { b3 = b; above = acc - hb[b]; break; }
        }
        s_b3 = b3; s_need3 = need2 - (int)above;
    }
    __syncthreads();
    int b3 = s_b3, need3 = s_need3;

    unsigned long long sum2 = 0ull;
    for (int sg = 0; sg < CHUNKS3; ++sg) {
        const float* sb = g_side + (size_t)(row * CHUNKS3 + sg) * CHUNK3;
        int cnt = (int)segc[sg];
        for (int i = tid; i < cnt; i += THREADS) {
            float v = sb[i];
            unsigned bits = nbits(v);
            if ((int)((bits >> 7) & 0xFFFu) == b2 && (int)(bits & 0x7Fu) > b3)
                sum2 += fx_of(v);
        }
    }
    red[tid] = sum2;
    __syncthreads();
    for (int st = THREADS / 2; st > 0; st >>= 1) {
        if (tid < st) red[tid] += red[tid + st];
        __syncthreads();
    }
    if (tid == 0) {
        unsigned tb = ((unsigned)g_bstar[row] << 19) | ((unsigned)b2 << 7) | (unsigned)b3;
        float tv = __uint_as_float(tb);
        unsigned long long contrib = sum_gt2 + red[0]
                                   + (unsigned long long)need3 * fx_of(tv);
        if (contrib) atomicAdd(&g_total, contrib * TOT_MUL);
    }
}

// -------- K5: finalize mean; zeroes g_total for next replay --------
__global__ void k5_final(float* out, const void* sp_ptr, int has_sp) {
    if (threadIdx.x == 0 && blockIdx.x == 0) {
        int m = decode_m(sp_ptr, has_sp);
        double tot = (double)g_total / FXD;
        out[0] = (float)(tot / ((double)ROWS * (double)m));
        g_total = 0ull;                              // self-clean for next replay
    }
}

extern "C" void kernel_launch(void* const* d_in, const int* in_sizes, int n_in,
                              void* d_out, int out_size) {
    const float* inp = (const float*)d_in[0];
    const int*   tgt = (const int*)d_in[1];
    const void*  sp  = (n_in > 2) ? d_in[2] : nullptr;
    int has_sp = (n_in > 2) ? 1 : 0;
    (void)in_sizes; (void)out_size;

    k1_nll<<<ROWS * CHUNKS1, THREADS>>>(inp, tgt);
    k2_thresh<<<ROWS, THREADS>>>(sp, has_sp);
    k3_sum<<<ROWS * CHUNKS3, THREADS>>>();
    k4_side<<<ROWS, THREADS>>>();
    k5_final<<<1, 32>>>((float*)d_out, sp, has_sp);
}

// round 9
// speedup vs baseline: 1.8438x; 1.8438x over previous
#include <cuda_runtime.h>
#include <cstdint>

// Problem constants (shapes fixed by the dataset problem)
#define ROWS 64            // B*N
#define PP   147456        // H*W
#define KCLS 3
#define NBIN 4096
#define THREADS 256

// k1 chunking
#define CHUNKS1 16
#define CHUNK1  (PP / CHUNKS1)           // 9216
#define ITERS1  (CHUNK1 / (THREADS*4))   // 9

// k3 chunking (finer: fewer regs, better occupancy/wave balance)
#define CHUNKS3 48
#define CHUNK3  (PP / CHUNKS3)           // 3072
#define ITERS3  (CHUNK3 / (THREADS*4))   // 3

#define K4_CACHE 8192                    // floats staged in smem by k4

#define FX_SCALE  4194304.0f             // 2^22 per-element fixed point
#define TOT_MUL   256ull                 // 2^22 -> 2^30 for g_total
#define FXD       1073741824.0           // 2^30

// -------- scratch (no allocations allowed; device globals; self-cleaning) ----
__device__ float g_nll [(size_t)ROWS * PP];
__device__ float g_side[(size_t)ROWS * PP];          // row-contiguous compaction
__device__ unsigned int g_hist[ROWS * NBIN];         // zeroed by k2 after use
__device__ unsigned int g_sidecnt[ROWS];             // zeroed by k4 after use
__device__ int g_bstar[ROWS];                        // overwritten by k2
__device__ int g_needed[ROWS];                       // overwritten by k2
__device__ unsigned long long g_total;               // zeroed by k5 after use

__device__ __forceinline__ unsigned int nbits(float v) {
    return (v > 0.0f) ? __float_as_uint(v) : 0u;     // nll >= 0
}

__device__ __forceinline__ unsigned long long fx_of(float v) {
    float c = fminf(v, 64.0f);                       // 46-bit safety cap
    return (unsigned long long)(c * FX_SCALE + 0.5f);
}

__device__ __forceinline__ float nllsel(int t, float a, float b, float c) {
    if (t == 255) return 0.0f;                       // ignore_index
    float v = (t == 0) ? a : (t == 1) ? b : c;
    return -v;
}

__device__ __forceinline__ int decode_m(const void* sp_ptr, int has_sp) {
    double sp = 1.0;
    if (has_sp) {
        unsigned int bits = *(const unsigned int*)sp_ptr;
        if (bits < 1024u) sp = (double)(int)bits;            // int32 scalar
        else              sp = (double)__uint_as_float(bits);// float32 scalar
    }
    if (sp > 1.0) sp = 1.0;
    if (sp < 0.0) sp = 0.0;
    double md = sp * 0.15 * (double)PP + (1.0 - sp) * (double)PP;
    int m = (int)md;
    if (m < 1) m = 1;
    if (m > PP) m = PP;
    return m;
}

// -------- K1: nll compute + buffer + per-row u32 histogram --------
__global__ void __launch_bounds__(THREADS) k1_nll(const float* __restrict__ inp,
                                                  const int*   __restrict__ tgt) {
    __shared__ unsigned int sh[NBIN];                // 16 KB
    for (int i = threadIdx.x; i < NBIN; i += THREADS) sh[i] = 0u;
    __syncthreads();

    int row = blockIdx.x / CHUNKS1;
    int seg = blockIdx.x % CHUNKS1;
    size_t tbase = (size_t)row * PP + (size_t)seg * CHUNK1;
    const float* p0 = inp + (size_t)row * KCLS * PP + (size_t)seg * CHUNK1;
    const float* p1 = p0 + PP;
    const float* p2 = p0 + 2 * PP;
    const int*   tg = tgt + tbase;
    float*       ob = g_nll + tbase;

    int off0 = threadIdx.x * 4;
    int4   t4 = *(const int4*)(tg + off0);
    float4 a  = *(const float4*)(p0 + off0);
    float4 b  = *(const float4*)(p1 + off0);
    float4 c  = *(const float4*)(p2 + off0);

#pragma unroll
    for (int it = 0; it < ITERS1; ++it) {
        int4 t4n; float4 an, bn, cn;
        if (it + 1 < ITERS1) {
            int offn = (it + 1) * (THREADS * 4) + threadIdx.x * 4;
            t4n = *(const int4*)(tg + offn);
            an  = *(const float4*)(p0 + offn);
            bn  = *(const float4*)(p1 + offn);
            cn  = *(const float4*)(p2 + offn);
        }
        int off = it * (THREADS * 4) + threadIdx.x * 4;
        float4 o;
        o.x = nllsel(t4.x, a.x, b.x, c.x);
        o.y = nllsel(t4.y, a.y, b.y, c.y);
        o.z = nllsel(t4.z, a.z, b.z, c.z);
        o.w = nllsel(t4.w, a.w, b.w, c.w);
        atomicAdd(&sh[nbits(o.x) >> 19], 1u);
        atomicAdd(&sh[nbits(o.y) >> 19], 1u);
        atomicAdd(&sh[nbits(o.z) >> 19], 1u);
        atomicAdd(&sh[nbits(o.w) >> 19], 1u);
        *(float4*)(ob + off) = o;
        t4 = t4n; a = an; b = bn; c = cn;
    }
    __syncthreads();
    for (int i = threadIdx.x; i < NBIN; i += THREADS) {
        unsigned int v = sh[i];
        if (v) atomicAdd(&g_hist[row * NBIN + i], v);
    }
}

// -------- K2: threshold bin via suffix scan; zeroes g_hist after use --------
__global__ void __launch_bounds__(THREADS) k2_thresh(const void* sp_ptr, int has_sp) {
    int row = blockIdx.x;
    __shared__ unsigned int sh[NBIN];
    __shared__ unsigned int cs[THREADS];
    for (int i = threadIdx.x; i < NBIN; i += THREADS) {
        sh[i] = g_hist[row * NBIN + i];
        g_hist[row * NBIN + i] = 0u;                 // self-clean for next replay
    }
    __syncthreads();
    unsigned s = 0;
    int base = threadIdx.x * (NBIN / THREADS);       // 16 bins each
    for (int j = 0; j < NBIN / THREADS; ++j) s += sh[base + j];
    cs[threadIdx.x] = s;
    __syncthreads();
    if (threadIdx.x == 0) {
        unsigned m = (unsigned)decode_m(sp_ptr, has_sp);
        unsigned acc = 0, above = 0;
        int bstar = 0;
        for (int j = THREADS - 1; j >= 0; --j) {
            if (acc + cs[j] >= m) {
                for (int b = j * 16 + 15; b >= j * 16; --b) {
                    acc += sh[b];
                    if (acc >= m) { bstar = b; above = acc - sh[b]; break; }
                }
                break;
            }
            acc += cs[j];
        }
        g_bstar[row]  = bstar;
        g_needed[row] = (int)m - (int)above;
    }
}

// -------- K3: fx-sum above bins; smem-staged compaction, one reserve/block ----
__global__ void __launch_bounds__(THREADS) k3_sum() {
    int row = blockIdx.x / CHUNKS3;
    unsigned bstar = (unsigned)g_bstar[row];
    size_t tbase = (size_t)row * PP + (size_t)(blockIdx.x % CHUNKS3) * CHUNK3;
    const float4* ib = (const float4*)(g_nll + tbase);
    float* gsb = g_side + (size_t)row * PP;          // row-contiguous output

    __shared__ float sbuf[CHUNK3];                   // 12 KB staging (worst case)
    __shared__ unsigned int scnt;
    __shared__ unsigned int gbase;
    __shared__ unsigned long long wred[THREADS / 32];
    if (threadIdx.x == 0) scnt = 0u;
    __syncthreads();

    // Front-batch loads: 3 independent LDG.128 per thread.
    float4 r[ITERS3];
#pragma unroll
    for (int it = 0; it < ITERS3; ++it)
        r[it] = ib[it * THREADS + threadIdx.x];

    unsigned long long fx = 0ull;
#pragma unroll
    for (int it = 0; it < ITERS3; ++it) {
        float vv[4] = {r[it].x, r[it].y, r[it].z, r[it].w};
#pragma unroll
        for (int e = 0; e < 4; ++e) {
            float v = vv[e];
            unsigned bin = nbits(v) >> 19;
            if (bin > bstar) {
                fx += fx_of(v);
            } else if (bin == bstar) {               // rare; block-local ATOMS
                unsigned idx = atomicAdd(&scnt, 1u);
                sbuf[idx] = v;
            }
        }
    }

    // warp shuffle reduction, then one cross-warp step
#pragma unroll
    for (int o = 16; o > 0; o >>= 1)
        fx += __shfl_xor_sync(0xffffffffu, fx, o);
    int wid = threadIdx.x >> 5;
    if ((threadIdx.x & 31) == 0) wred[wid] = fx;
    __syncthreads();
    if (threadIdx.x == 0) {
        unsigned long long t = 0ull;
#pragma unroll
        for (int w = 0; w < THREADS / 32; ++w) t += wred[w];
        if (t) atomicAdd(&g_total, t * TOT_MUL);
        gbase = scnt ? atomicAdd(&g_sidecnt[row], scnt) : 0u;  // one reserve/block
    }
    __syncthreads();
    // coalesced copy of staged matches into row-contiguous side buffer
    unsigned n = scnt, b0 = gbase;
    for (unsigned i = threadIdx.x; i < n; i += THREADS)
        gsb[b0 + i] = sbuf[i];
}

// -------- K4: exact select in threshold bin; flat side array, smem-cached -----
__global__ void __launch_bounds__(THREADS) k4_side() {
    int row = blockIdx.x;
    int tid = threadIdx.x;
    int cnt = (int)g_sidecnt[row];
    int needed = g_needed[row];
    __syncthreads();
    if (tid == 0) g_sidecnt[row] = 0u;               // self-clean for next replay
    if (needed <= 0) return;

    const float* gsb = g_side + (size_t)row * PP;
    __shared__ float vc[K4_CACHE];                   // 32 KB value cache
    bool cached = (cnt <= K4_CACHE);
    if (cached)
        for (int i = tid; i < cnt; i += THREADS) vc[i] = gsb[i];

    __shared__ unsigned int h[NBIN];
    __shared__ unsigned int cs[THREADS];
    __shared__ unsigned long long red[THREADS];
    __shared__ unsigned int hb[128];
    __shared__ int s_b2, s_need2, s_b3, s_need3;

    for (int i = tid; i < NBIN; i += THREADS) h[i] = 0u;
    __syncthreads();
    for (int i = tid; i < cnt; i += THREADS) {
        float v = cached ? vc[i] : gsb[i];
        atomicAdd(&h[(nbits(v) >> 7) & 0xFFFu], 1u);
    }
    __syncthreads();
    unsigned s = 0;
    int base = tid * (NBIN / THREADS);
    for (int j = 0; j < NBIN / THREADS; ++j) s += h[base + j];
    cs[tid] = s;
    __syncthreads();
    if (tid == 0) {
        unsigned acc = 0, above = 0; int b2 = 0;
        for (int j = THREADS - 1; j >= 0; --j) {
            if (acc + cs[j] >= (unsigned)needed) {
                for (int b = j * 16 + 15; b >= j * 16; --b) {
                    acc += h[b];
                    if (acc >= (unsigned)needed) { b2 = b; above = acc - h[b]; break; }
                }
                break;
            }
            acc += cs[j];
        }
        s_b2 = b2; s_need2 = needed - (int)above;
    }
    for (int i = tid; i < 128; i += THREADS) hb[i] = 0u;
    __syncthreads();
    int b2 = s_b2, need2 = s_need2;

    unsigned long long sum1 = 0ull;
    for (int i = tid; i < cnt; i += THREADS) {
        float v = cached ? vc[i] : gsb[i];
        unsigned bits = nbits(v);
        int b = (int)((bits >> 7) & 0xFFFu);
        if (b > b2) sum1 += fx_of(v);
        else if (b == b2) atomicAdd(&hb[bits & 0x7Fu], 1u);
    }
    red[tid] = sum1;
    __syncthreads();
    for (int st = THREADS / 2; st > 0; st >>= 1) {
        if (tid < st) red[tid] += red[tid + st];
        __syncthreads();
    }
    unsigned long long sum_gt2 = red[0];   // read by all before next barrier pass
    if (tid == 0) {
        unsigned acc = 0, above = 0; int b3 = 0;
        for (int b = 127; b >= 0; --b) {
            acc += hb[b];
            if (acc >= (unsigned)need2) { b3 = b; above = acc - hb[b]; break; }
        }
        s_b3 = b3; s_need3 = need2 - (int)above;
    }
    __syncthreads();
    int b3 = s_b3, need3 = s_need3;

    unsigned long long sum2 = 0ull;
    for (int i = tid; i < cnt; i += THREADS) {
        float v = cached ? vc[i] : gsb[i];
        unsigned bits = nbits(v);
        if ((int)((bits >> 7) & 0xFFFu) == b2 && (int)(bits & 0x7Fu) > b3)
            sum2 += fx_of(v);
    }
    red[tid] = sum2;
    __syncthreads();
    for (int st = THREADS / 2; st > 0; st >>= 1) {
        if (tid < st) red[tid] += red[tid + st];
        __syncthreads();
    }
    if (tid == 0) {
        unsigned tb = ((unsigned)g_bstar[row] << 19) | ((unsigned)b2 << 7) | (unsigned)b3;
        float tv = __uint_as_float(tb);
        unsigned long long contrib = sum_gt2 + red[0]
                                   + (unsigned long long)need3 * fx_of(tv);
        if (contrib) atomicAdd(&g_total, contrib * TOT_MUL);
    }
}

// -------- K5: finalize mean; zeroes g_total for next replay --------
__global__ void k5_final(float* out, const void* sp_ptr, int has_sp) {
    if (threadIdx.x == 0 && blockIdx.x == 0) {
        int m = decode_m(sp_ptr, has_sp);
        double tot = (double)g_total / FXD;
        out[0] = (float)(tot / ((double)ROWS * (double)m));
        g_total = 0ull;                              // self-clean for next replay
    }
}

extern "C" void kernel_launch(void* const* d_in, const int* in_sizes, int n_in,
                              void* d_out, int out_size) {
    const float* inp = (const float*)d_in[0];
    const int*   tgt = (const int*)d_in[1];
    const void*  sp  = (n_in > 2) ? d_in[2] : nullptr;
    int has_sp = (n_in > 2) ? 1 : 0;
    (void)in_sizes; (void)out_size;

    k1_nll<<<ROWS * CHUNKS1, THREADS>>>(inp, tgt);
    k2_thresh<<<ROWS, THREADS>>>(sp, has_sp);
    k3_sum<<<ROWS * CHUNKS3, THREADS>>>();
    k4_side<<<ROWS, THREADS>>>();
    k5_final<<<1, 32>>>((float*)d_out, sp, has_sp);
}